// round 1
// baseline (speedup 1.0000x reference)
#include <cuda_runtime.h>
#include <math.h>

// Problem constants
constexpr int T   = 64;
constexpr int B   = 2048;
constexpr int H   = 256;
constexpr int H1  = 64;
constexpr int H2  = 64;
constexpr int OUTD = 601;

// GRU tiling
constexpr int TB = 32;   // batches per block
constexpr int TJ = 64;   // hidden columns per block
constexpr int KK = 32;   // k chunk
constexpr int WCP = KK + 4;           // padded kk stride (36) -> conflict-free LDS.128
constexpr int GRU_SMEM = (TB*H + 3*TJ*WCP) * 4;   // 32KB + 27KB = 60416 B

// MLP tiling
constexpr int RROWS = 64;  // rows per block
// dynamic smem layout (floats):
//   xt  @ 0       : RROWS*H      = 16384   (reused by w3s tile: 64*128 = 8192)
//   w1s @ 16384   : 64*260       = 16640   (reused by w2s: 64*68 = 4352)
//   h1s @ 33024   : RROWS*64     = 4096
//   h2s @ 37120   : RROWS*64     = 4096
constexpr int MLP_SMEM = (16384 + 16640 + 4096 + 4096) * 4;  // 164864 B

// Scratch: GRU hidden states for all timesteps (also feeds the MLP).
__device__ float g_ys[(size_t)T * B * H];   // 128 MB

// ---------------------------------------------------------------------------
// GRU step: h_t = GRUCell(x_t, h_{t-1}).  One launch per timestep.
// Reads h_{t-1} from g_ys[t-1] (or h0 for t=0), writes h_t into g_ys[t].
// ---------------------------------------------------------------------------
__global__ void __launch_bounds__(256)
gru_step_kernel(int t,
                const float* __restrict__ h0,
                const float* __restrict__ x,
                const float* __restrict__ w_hh,
                const float* __restrict__ w_ih,
                const float* __restrict__ b_ih,
                const float* __restrict__ b_hh)
{
    extern __shared__ float sm[];
    float* hs = sm;                 // [TB][H]
    float* wc = sm + TB * H;        // [3][TJ][WCP]

    const float* hprev = (t == 0) ? h0 : (g_ys + (size_t)(t - 1) * B * H);
    float* hout = g_ys + (size_t)t * B * H;

    const int j0  = blockIdx.x * TJ;
    const int b0  = blockIdx.y * TB;
    const int tid = threadIdx.x;

    // Load h tile (coalesced float4 copy)
    {
        const float4* src = (const float4*)(hprev + (size_t)b0 * H);
        float4* dst = (float4*)hs;
        #pragma unroll
        for (int i = tid; i < TB * H / 4; i += 256) dst[i] = src[i];
    }

    const int j  = tid & (TJ - 1);   // 0..63 hidden col within tile
    const int bg = tid >> 6;         // 0..3 batch group (8 batches each)

    float accr[8], accz[8], accn[8];
    #pragma unroll
    for (int i = 0; i < 8; i++) { accr[i] = 0.f; accz[i] = 0.f; accn[i] = 0.f; }

    for (int k0 = 0; k0 < H; k0 += KK) {
        __syncthreads();   // protects hs load (1st iter) and wc reuse
        // Stage w_hh chunk: wc[g][jj][kk], coalesced global reads
        #pragma unroll
        for (int f = tid; f < 3 * TJ * KK; f += 256) {
            int kk = f & (KK - 1);
            int jj = (f >> 5) & (TJ - 1);
            int g  = f >> 11;
            wc[(g * TJ + jj) * WCP + kk] =
                w_hh[((size_t)(g * H + j0 + jj)) * H + k0 + kk];
        }
        __syncthreads();

        #pragma unroll
        for (int kk = 0; kk < KK; kk += 4) {
            float4 wr4 = *(const float4*)&wc[(0 * TJ + j) * WCP + kk];
            float4 wz4 = *(const float4*)&wc[(1 * TJ + j) * WCP + kk];
            float4 wn4 = *(const float4*)&wc[(2 * TJ + j) * WCP + kk];
            #pragma unroll
            for (int i = 0; i < 8; i++) {
                float4 hv = *(const float4*)&hs[(bg * 8 + i) * H + k0 + kk];
                accr[i] += hv.x * wr4.x; accz[i] += hv.x * wz4.x; accn[i] += hv.x * wn4.x;
                accr[i] += hv.y * wr4.y; accz[i] += hv.y * wz4.y; accn[i] += hv.y * wn4.y;
                accr[i] += hv.z * wr4.z; accz[i] += hv.z * wz4.z; accn[i] += hv.z * wn4.z;
                accr[i] += hv.w * wr4.w; accz[i] += hv.w * wz4.w; accn[i] += hv.w * wn4.w;
            }
        }
    }

    // Epilogue: gates + state update
    const int jg = j0 + j;
    const float xw_r = w_ih[jg];
    const float xw_z = w_ih[H + jg];
    const float xw_n = w_ih[2 * H + jg];
    const float bb_r = b_ih[jg]       + b_hh[jg];
    const float bb_z = b_ih[H + jg]   + b_hh[H + jg];
    const float bi_n = b_ih[2 * H + jg];
    const float bh_n = b_hh[2 * H + jg];

    #pragma unroll
    for (int i = 0; i < 8; i++) {
        int bl = bg * 8 + i;
        float xv = x[(size_t)t * B + b0 + bl];
        float r = 1.f / (1.f + expf(-(xv * xw_r + bb_r + accr[i])));
        float z = 1.f / (1.f + expf(-(xv * xw_z + bb_z + accz[i])));
        float n = tanhf(xv * xw_n + bi_n + r * (accn[i] + bh_n));
        float hold = hs[bl * H + jg];
        float hnew = (1.f - z) * n + z * hold;
        hout[(size_t)(b0 + bl) * H + jg] = hnew;
    }
}

// ---------------------------------------------------------------------------
// Fused MLP: y = elu(elu(ys@w1+b1)@w2+b2)@w3 + b3, over all T*B rows.
// ---------------------------------------------------------------------------
__global__ void __launch_bounds__(256)
mlp_kernel(const float* __restrict__ w1, const float* __restrict__ b1,
           const float* __restrict__ w2, const float* __restrict__ b2,
           const float* __restrict__ w3, const float* __restrict__ b3,
           float* __restrict__ out)
{
    extern __shared__ float sm[];
    float* xt  = sm;            // [RROWS][H]
    float* w1s = sm + 16384;    // [64][260] transposed w1
    float* h1s = sm + 33024;    // [RROWS][64]
    float* h2s = sm + 37120;    // [RROWS][64]
    float* w3s = sm;            // alias xt: [64][128]
    float* w2s = sm + 16384;    // alias w1s: [64][68]

    const int tid = threadIdx.x;
    const size_t row0 = (size_t)blockIdx.x * RROWS;

    // Load input rows + w1 (transposed, padded)
    {
        const float4* src = (const float4*)(g_ys + row0 * H);
        float4* dst = (float4*)xt;
        for (int i = tid; i < RROWS * H / 4; i += 256) dst[i] = src[i];
    }
    for (int f = tid; f < H * H1; f += 256) {
        int jj = f & 63; int k = f >> 6;
        w1s[jj * 260 + k] = w1[f];
    }
    __syncthreads();

    const int jp = tid & 31;    // column pair: j = 2jp, 2jp+1
    const int rg = tid >> 5;    // row group: rows rg*8 .. rg*8+7

    // ---- Stage 1: h1 = elu(xt @ w1 + b1) ----
    {
        float acc[8][2];
        #pragma unroll
        for (int i = 0; i < 8; i++) { acc[i][0] = 0.f; acc[i][1] = 0.f; }
        #pragma unroll 4
        for (int k = 0; k < H; k += 4) {
            float4 wa = *(const float4*)&w1s[(2 * jp) * 260 + k];
            float4 wb = *(const float4*)&w1s[(2 * jp + 1) * 260 + k];
            #pragma unroll
            for (int i = 0; i < 8; i++) {
                float4 xv = *(const float4*)&xt[(rg * 8 + i) * H + k];
                acc[i][0] += xv.x * wa.x + xv.y * wa.y + xv.z * wa.z + xv.w * wa.w;
                acc[i][1] += xv.x * wb.x + xv.y * wb.y + xv.z * wb.z + xv.w * wb.w;
            }
        }
        float ba = b1[2 * jp], bb = b1[2 * jp + 1];
        #pragma unroll
        for (int i = 0; i < 8; i++) {
            float va = acc[i][0] + ba; va = va > 0.f ? va : expm1f(va);
            float vb = acc[i][1] + bb; vb = vb > 0.f ? vb : expm1f(vb);
            h1s[(rg * 8 + i) * 64 + 2 * jp]     = va;
            h1s[(rg * 8 + i) * 64 + 2 * jp + 1] = vb;
        }
    }
    __syncthreads();   // stage1 readers of xt/w1s done before aliasing writes

    // Load w2 (transposed, padded) into w1s region
    for (int f = tid; f < H1 * H2; f += 256) {
        int jj = f & 63; int k = f >> 6;
        w2s[jj * 68 + k] = w2[f];
    }
    __syncthreads();

    // ---- Stage 2: h2 = elu(h1 @ w2 + b2) ----
    {
        float acc[8][2];
        #pragma unroll
        for (int i = 0; i < 8; i++) { acc[i][0] = 0.f; acc[i][1] = 0.f; }
        #pragma unroll
        for (int k = 0; k < H1; k += 4) {
            float4 wa = *(const float4*)&w2s[(2 * jp) * 68 + k];
            float4 wb = *(const float4*)&w2s[(2 * jp + 1) * 68 + k];
            #pragma unroll
            for (int i = 0; i < 8; i++) {
                float4 xv = *(const float4*)&h1s[(rg * 8 + i) * 64 + k];
                acc[i][0] += xv.x * wa.x + xv.y * wa.y + xv.z * wa.z + xv.w * wa.w;
                acc[i][1] += xv.x * wb.x + xv.y * wb.y + xv.z * wb.z + xv.w * wb.w;
            }
        }
        float ba = b2[2 * jp], bb = b2[2 * jp + 1];
        #pragma unroll
        for (int i = 0; i < 8; i++) {
            float va = acc[i][0] + ba; va = va > 0.f ? va : expm1f(va);
            float vb = acc[i][1] + bb; vb = vb > 0.f ? vb : expm1f(vb);
            h2s[(rg * 8 + i) * 64 + 2 * jp]     = va;
            h2s[(rg * 8 + i) * 64 + 2 * jp + 1] = vb;
        }
    }
    __syncthreads();

    // ---- Stage 3: y = h2 @ w3 + b3, tiled over 601 output cols ----
    const int cp  = tid & 31;   // 4 consecutive cols: cp*4 .. cp*4+3
    const int rg3 = tid >> 5;

    for (int c0 = 0; c0 < OUTD; c0 += 128) {
        // load w3 tile [64][128] into w3s (aliases xt; prior sync protects)
        for (int f = tid; f < 64 * 128; f += 256) {
            int c = f & 127; int k = f >> 7;
            int cg = c0 + c;
            w3s[k * 128 + c] = (cg < OUTD) ? w3[(size_t)k * OUTD + cg] : 0.f;
        }
        __syncthreads();

        float acc[8][4];
        #pragma unroll
        for (int i = 0; i < 8; i++)
            #pragma unroll
            for (int q = 0; q < 4; q++) acc[i][q] = 0.f;

        #pragma unroll 4
        for (int k = 0; k < H2; k += 4) {
            float4 wv0 = *(const float4*)&w3s[(k + 0) * 128 + cp * 4];
            float4 wv1 = *(const float4*)&w3s[(k + 1) * 128 + cp * 4];
            float4 wv2 = *(const float4*)&w3s[(k + 2) * 128 + cp * 4];
            float4 wv3 = *(const float4*)&w3s[(k + 3) * 128 + cp * 4];
            #pragma unroll
            for (int i = 0; i < 8; i++) {
                float4 hv = *(const float4*)&h2s[(rg3 * 8 + i) * 64 + k];
                acc[i][0] += hv.x * wv0.x + hv.y * wv1.x + hv.z * wv2.x + hv.w * wv3.x;
                acc[i][1] += hv.x * wv0.y + hv.y * wv1.y + hv.z * wv2.y + hv.w * wv3.y;
                acc[i][2] += hv.x * wv0.z + hv.y * wv1.z + hv.z * wv2.z + hv.w * wv3.z;
                acc[i][3] += hv.x * wv0.w + hv.y * wv1.w + hv.z * wv2.w + hv.w * wv3.w;
            }
        }

        #pragma unroll
        for (int i = 0; i < 8; i++) {
            size_t row = row0 + rg3 * 8 + i;
            #pragma unroll
            for (int q = 0; q < 4; q++) {
                int cg = c0 + cp * 4 + q;
                if (cg < OUTD) out[row * OUTD + cg] = acc[i][q] + b3[cg];
            }
        }
        __syncthreads();   // before next tile overwrites w3s
    }
}

// Copy final hidden state h_T into the tail of the output.
__global__ void copy_h_kernel(float* __restrict__ out)
{
    int i = blockIdx.x * blockDim.x + threadIdx.x;
    if (i < B * H / 4) {
        const float4* src = (const float4*)(g_ys + (size_t)(T - 1) * B * H);
        ((float4*)out)[i] = src[i];
    }
}

// ---------------------------------------------------------------------------
extern "C" void kernel_launch(void* const* d_in, const int* in_sizes, int n_in,
                              void* d_out, int out_size)
{
    const float* x    = (const float*)d_in[0];
    const float* h0   = (const float*)d_in[1];
    const float* w_ih = (const float*)d_in[2];
    const float* w_hh = (const float*)d_in[3];
    const float* b_ih = (const float*)d_in[4];
    const float* b_hh = (const float*)d_in[5];
    const float* w1   = (const float*)d_in[6];
    const float* b1   = (const float*)d_in[7];
    const float* w2   = (const float*)d_in[8];
    const float* b2   = (const float*)d_in[9];
    const float* w3   = (const float*)d_in[10];
    const float* b3   = (const float*)d_in[11];
    float* out = (float*)d_out;

    cudaFuncSetAttribute(gru_step_kernel,
                         cudaFuncAttributeMaxDynamicSharedMemorySize, GRU_SMEM);
    cudaFuncSetAttribute(mlp_kernel,
                         cudaFuncAttributeMaxDynamicSharedMemorySize, MLP_SMEM);

    dim3 ggrid(H / TJ, B / TB);   // (4, 64)
    for (int t = 0; t < T; ++t) {
        gru_step_kernel<<<ggrid, 256, GRU_SMEM>>>(t, h0, x, w_hh, w_ih, b_ih, b_hh);
    }

    mlp_kernel<<<(T * B) / RROWS, 256, MLP_SMEM>>>(w1, b1, w2, b2, w3, b3, out);

    copy_h_kernel<<<(B * H / 4 + 255) / 256, 256>>>(out + (size_t)T * B * OUTD);
}